// round 5
// baseline (speedup 1.0000x reference)
#include <cuda_runtime.h>
#include <cuda_bf16.h>

// Problem constants
#define BB  4
#define CX  16
#define CA  8
#define C1  16
#define NN  1024
#define DD  64
#define NEGINF (-3.402823466e38f)

// 0.02*sigmoid(z) = 0.01 + 0.01*tanh(z/2); z = S*mm/sqrt(10)
// -> store S' = S * 0.5/sqrt(10), A' = Amean + 0.01; out = fma(0.01, tanh(S'*mm), A')
#define SSCALE 0.15811388300841898f

// Scratch (static __device__ arrays; no dynamic allocation)
__device__ __align__(16) float g_Sp[8u * BB * NN * NN];            // 134 MB partial S
__device__ __align__(16) float g_SA[2u * BB * NN * NN];            // 33.6 MB (S',A') interleaved
__device__ __align__(16) __nv_bfloat16 g_xbf[BB * CX * NN * DD];   // 8.4 MB
__device__ __align__(16) __nv_bfloat16 g_mbf[BB * C1 * NN * DD];   // 8.4 MB

// ---------------------------------------------------------------------------
// PTX helpers
// ---------------------------------------------------------------------------
__device__ __forceinline__ unsigned sptr(const void* p) {
    return (unsigned)__cvta_generic_to_shared(p);
}

__device__ __forceinline__ void ldsm4(unsigned a[4], unsigned addr) {
    asm volatile("ldmatrix.sync.aligned.m8n8.x4.shared.b16 {%0,%1,%2,%3}, [%4];"
                 : "=r"(a[0]), "=r"(a[1]), "=r"(a[2]), "=r"(a[3]) : "r"(addr));
}

__device__ __forceinline__ void mma16816(float c[4], const unsigned a[4],
                                         unsigned b0, unsigned b1) {
    asm volatile(
        "mma.sync.aligned.m16n8k16.row.col.f32.bf16.bf16.f32 "
        "{%0,%1,%2,%3}, {%4,%5,%6,%7}, {%8,%9}, {%0,%1,%2,%3};"
        : "+f"(c[0]), "+f"(c[1]), "+f"(c[2]), "+f"(c[3])
        : "r"(a[0]), "r"(a[1]), "r"(a[2]), "r"(a[3]), "r"(b0), "r"(b1));
}

__device__ __forceinline__ void cpasync16(unsigned dst, const void* src) {
    asm volatile("cp.async.cg.shared.global [%0], [%1], 16;" :: "r"(dst), "l"(src));
}
#define CP_COMMIT() asm volatile("cp.async.commit_group;")
#define CP_WAIT1()  asm volatile("cp.async.wait_group 1;")
#define CP_WAIT0()  asm volatile("cp.async.wait_group 0;")

__device__ __forceinline__ float tanhap(float x) {
    float r;
    asm("tanh.approx.f32 %0, %1;" : "=f"(r) : "f"(x));
    return r;
}

// ---------------------------------------------------------------------------
// Swizzled bf16 tiles: [rows][64] bf16, 128B/row; 16B chunk' = chunk ^ (row&7)
// ---------------------------------------------------------------------------
__device__ __forceinline__ void pf_tile128(const __nv_bfloat16* src,
                                           __nv_bfloat16* dst, int tid) {
#pragma unroll
    for (int q = 0; q < 4; q++) {
        int id = tid + q * 256;
        int r = id >> 3, cc = id & 7;
        cpasync16(sptr(dst + r * 64 + ((cc ^ (r & 7)) << 3)), src + r * 64 + cc * 8);
    }
}

__device__ __forceinline__ void pf_tile64(const __nv_bfloat16* src,
                                          __nv_bfloat16* dst, int tid) {
#pragma unroll
    for (int q = 0; q < 2; q++) {
        int id = tid + q * 256;
        int r = id >> 3, cc = id & 7;
        cpasync16(sptr(dst + r * 64 + ((cc ^ (r & 7)) << 3)), src + r * 64 + cc * 8);
    }
}

// A fragments for a 16-row slice, cached in regs
__device__ __forceinline__ void load_afrag(const __nv_bfloat16* xi16, int lane,
                                           unsigned a[4][4]) {
    const int ar = (lane & 7) + (((lane >> 3) & 1) << 3);
    const int ak8 = lane >> 4;
#pragma unroll
    for (int ks = 0; ks < 4; ks++)
        ldsm4(a[ks], sptr(xi16 + ar * 64 + (((2 * ks + ak8) ^ (ar & 7)) << 3)));
}

// acc[8] += A(16x64) * B(rows n0..n0+15 of 64x64 tile)^T
__device__ __forceinline__ void subtile_mma(const __nv_bfloat16* bt, int n0, int lane,
                                            const unsigned a[4][4], float acc[8]) {
    const int m = lane >> 3;
    const int br = n0 + (lane & 7) + ((m >> 1) << 3);
    const int bk8 = m & 1;
#pragma unroll
    for (int ks = 0; ks < 4; ks++) {
        unsigned b[4];
        ldsm4(b, sptr(bt + br * 64 + (((2 * ks + bk8) ^ (br & 7)) << 3)));
        mma16816(acc, a[ks], b[0], b[1]);
        mma16816(acc + 4, a[ks], b[2], b[3]);
    }
}

// ---------------------------------------------------------------------------
// Prep: bf16 conversion of x and mask in one kernel
// ---------------------------------------------------------------------------
#define NX4 (BB * CX * NN * DD / 4)
#define NM4 (BB * C1 * NN * DD / 4)
__global__ void k_conv(const float* __restrict__ x, const float* __restrict__ mask) {
    int idx = blockIdx.x * blockDim.x + threadIdx.x;
    const float4* src;
    uint2* dst;
    int i;
    if (idx < NX4) { src = (const float4*)x; dst = (uint2*)g_xbf; i = idx; }
    else if (idx < NX4 + NM4) { src = (const float4*)mask; dst = (uint2*)g_mbf; i = idx - NX4; }
    else return;
    float4 v = src[i];
    __nv_bfloat162 p0 = __floats2bfloat162_rn(v.x, v.y);
    __nv_bfloat162 p1 = __floats2bfloat162_rn(v.z, v.w);
    uint2 u;
    u.x = *reinterpret_cast<unsigned*>(&p0);
    u.y = *reinterpret_cast<unsigned*>(&p1);
    dst[i] = u;
}

// ---------------------------------------------------------------------------
// k_S3: partial S for 2 channels, 64-row tiles.
// grid (itile=16, cg=8, b=4) = 512 blocks, 256 thr.
// ---------------------------------------------------------------------------
#define KS3_SMEM (2*64*64*2 + 2*2*64*64*2 + 2*64*4 + 2*64*2*4 + 2*64*4)

__global__ void __launch_bounds__(256, 3) k_S3() {
    extern __shared__ char sm[];
    __nv_bfloat16* xi  = (__nv_bfloat16*)sm;            // [2ch][64*64]
    __nv_bfloat16* xjb = xi + 2 * 64 * 64;              // [2buf][2ch][64*64]
    float* P  = (float*)(xjb + 2 * 2 * 64 * 64);        // [2][64]
    float* Zw = P + 2 * 64;                             // [2][64][2]
    float* Zi = Zw + 2 * 64 * 2;                        // [2][64]

    const int tid = threadIdx.x, lane = tid & 31, w = tid >> 5;
    const int wr = w & 3, wc = w >> 2;
    const int itile = blockIdx.x, cg = blockIdx.y, b = blockIdx.z;

    const __nv_bfloat16* xc0 = g_xbf + (size_t)(b * CX + cg * 2) * NN * DD;
    const __nv_bfloat16* xc1 = xc0 + NN * DD;

    pf_tile64(xc0 + itile * 64 * 64, xi, tid);
    pf_tile64(xc1 + itile * 64 * 64, xi + 64 * 64, tid);
    CP_COMMIT();
    pf_tile64(xc0, xjb, tid);
    pf_tile64(xc1, xjb + 64 * 64, tid);
    CP_COMMIT();
    CP_WAIT1();
    __syncthreads();

    // P = ||row||^2 from bf16 values
    if (tid < 128) {
        int c = tid >> 6, r = tid & 63;
        const __nv_bfloat16* row = xi + c * 4096 + r * 64;
        float s = 0.f;
#pragma unroll
        for (int cc = 0; cc < 8; cc++) {
            const __nv_bfloat16* ch = row + ((cc ^ (r & 7)) << 3);
#pragma unroll
            for (int e = 0; e < 8; e++) {
                float v = __bfloat162float(ch[e]);
                s += v * v;
            }
        }
        P[c * 64 + r] = s;
    }
    __syncthreads();

    unsigned a0[4][4], a1[4][4];
    load_afrag(xi + wr * 16 * 64, lane, a0);
    load_afrag(xi + 4096 + wr * 16 * 64, lane, a1);

    const int lr0 = wr * 16 + (lane >> 2), lr1 = lr0 + 8;
    const float p00 = P[lr0], p01 = P[lr1], p10 = P[64 + lr0], p11 = P[64 + lr1];

    // ---- Pass Z ----
    float z00 = 0.f, z01 = 0.f, z10 = 0.f, z11 = 0.f;
    for (int jt = 0; jt < 16; jt++) {
        if (jt < 15) {
            __nv_bfloat16* nb = xjb + ((jt + 1) & 1) * 8192;
            pf_tile64(xc0 + (jt + 1) * 64 * 64, nb, tid);
            pf_tile64(xc1 + (jt + 1) * 64 * 64, nb + 4096, tid);
            CP_COMMIT(); CP_WAIT1();
        } else CP_WAIT0();
        __syncthreads();
        const __nv_bfloat16* bt = xjb + (jt & 1) * 8192;
#pragma unroll
        for (int nn = 0; nn < 2; nn++) {
            const int n0 = (wc * 2 + nn) * 16;
            {
                float acc[8] = {0.f, 0.f, 0.f, 0.f, 0.f, 0.f, 0.f, 0.f};
                subtile_mma(bt, n0, lane, a0, acc);
                z00 += __expf(acc[0] - p00) + __expf(acc[1] - p00)
                     + __expf(acc[4] - p00) + __expf(acc[5] - p00);
                z01 += __expf(acc[2] - p01) + __expf(acc[3] - p01)
                     + __expf(acc[6] - p01) + __expf(acc[7] - p01);
            }
            {
                float acc[8] = {0.f, 0.f, 0.f, 0.f, 0.f, 0.f, 0.f, 0.f};
                subtile_mma(bt + 4096, n0, lane, a1, acc);
                z10 += __expf(acc[0] - p10) + __expf(acc[1] - p10)
                     + __expf(acc[4] - p10) + __expf(acc[5] - p10);
                z11 += __expf(acc[2] - p11) + __expf(acc[3] - p11)
                     + __expf(acc[6] - p11) + __expf(acc[7] - p11);
            }
        }
        __syncthreads();
    }
    z00 += __shfl_xor_sync(0xffffffffu, z00, 1); z00 += __shfl_xor_sync(0xffffffffu, z00, 2);
    z01 += __shfl_xor_sync(0xffffffffu, z01, 1); z01 += __shfl_xor_sync(0xffffffffu, z01, 2);
    z10 += __shfl_xor_sync(0xffffffffu, z10, 1); z10 += __shfl_xor_sync(0xffffffffu, z10, 2);
    z11 += __shfl_xor_sync(0xffffffffu, z11, 1); z11 += __shfl_xor_sync(0xffffffffu, z11, 2);
    if ((lane & 3) == 0) {
        Zw[lr0 * 2 + wc]       = z00;
        Zw[lr1 * 2 + wc]       = z01;
        Zw[128 + lr0 * 2 + wc] = z10;
        Zw[128 + lr1 * 2 + wc] = z11;
    }
    __syncthreads();
    if (tid < 128) {
        int c = tid >> 6, r = tid & 63;
        Zi[c * 64 + r] = 1.f / (16.f * (Zw[c * 128 + r * 2] + Zw[c * 128 + r * 2 + 1]));
    }
    pf_tile64(xc0, xjb, tid);
    pf_tile64(xc1, xjb + 4096, tid);
    CP_COMMIT();
    __syncthreads();

    const float zi00 = Zi[lr0], zi01 = Zi[lr1];
    const float zi10 = Zi[64 + lr0], zi11 = Zi[64 + lr1];

    float* spBase = g_Sp + (size_t)(cg * BB + b) * NN * NN + (size_t)(itile * 64) * NN;

    for (int jt = 0; jt < 16; jt++) {
        if (jt < 15) {
            __nv_bfloat16* nb = xjb + ((jt + 1) & 1) * 8192;
            pf_tile64(xc0 + (jt + 1) * 64 * 64, nb, tid);
            pf_tile64(xc1 + (jt + 1) * 64 * 64, nb + 4096, tid);
            CP_COMMIT(); CP_WAIT1();
        } else CP_WAIT0();
        __syncthreads();
        const __nv_bfloat16* bt = xjb + (jt & 1) * 8192;

#pragma unroll
        for (int nn = 0; nn < 2; nn++) {
            const int n = wc * 2 + nn;
            float Sa[8];
#pragma unroll
            for (int k = 0; k < 8; k++) Sa[k] = 0.f;
            {
                float acc[8] = {0.f, 0.f, 0.f, 0.f, 0.f, 0.f, 0.f, 0.f};
                subtile_mma(bt, n * 16, lane, a0, acc);
                Sa[0] += __expf(acc[0] - p00) * zi00;
                Sa[1] += __expf(acc[1] - p00) * zi00;
                Sa[4] += __expf(acc[4] - p00) * zi00;
                Sa[5] += __expf(acc[5] - p00) * zi00;
                Sa[2] += __expf(acc[2] - p01) * zi01;
                Sa[3] += __expf(acc[3] - p01) * zi01;
                Sa[6] += __expf(acc[6] - p01) * zi01;
                Sa[7] += __expf(acc[7] - p01) * zi01;
            }
            {
                float acc[8] = {0.f, 0.f, 0.f, 0.f, 0.f, 0.f, 0.f, 0.f};
                subtile_mma(bt + 4096, n * 16, lane, a1, acc);
                Sa[0] += __expf(acc[0] - p10) * zi10;
                Sa[1] += __expf(acc[1] - p10) * zi10;
                Sa[4] += __expf(acc[4] - p10) * zi10;
                Sa[5] += __expf(acc[5] - p10) * zi10;
                Sa[2] += __expf(acc[2] - p11) * zi11;
                Sa[3] += __expf(acc[3] - p11) * zi11;
                Sa[6] += __expf(acc[6] - p11) * zi11;
                Sa[7] += __expf(acc[7] - p11) * zi11;
            }
            const int cb = jt * 64 + n * 16 + 2 * (lane & 3);
            *(float2*)(spBase + (size_t)lr0 * NN + cb)     = make_float2(Sa[0], Sa[1]);
            *(float2*)(spBase + (size_t)lr0 * NN + cb + 8) = make_float2(Sa[4], Sa[5]);
            *(float2*)(spBase + (size_t)lr1 * NN + cb)     = make_float2(Sa[2], Sa[3]);
            *(float2*)(spBase + (size_t)lr1 * NN + cb + 8) = make_float2(Sa[6], Sa[7]);
        }
        __syncthreads();
    }
}

// ---------------------------------------------------------------------------
// k_sreduce2: sum 8 partial S slices + mean of A over CA, write interleaved
// (S*SSCALE, Amean+0.01) pairs.
// ---------------------------------------------------------------------------
__global__ void k_sreduce2(const float* __restrict__ A) {
    int i = blockIdx.x * 256 + threadIdx.x;
    const int per_b = NN * NN / 4;
    int b = i / per_b;
    int r = i - b * per_b;

    const float4* sp = (const float4*)g_Sp;
    float4 s = sp[(size_t)b * per_b + r];
#pragma unroll
    for (int g = 1; g < 8; g++) {
        float4 v = sp[(size_t)(g * BB + b) * per_b + r];
        s.x += v.x; s.y += v.y; s.z += v.z; s.w += v.w;
    }
    const float4* ap = (const float4*)A + (size_t)b * CA * per_b + r;
    float4 a = ap[0];
#pragma unroll
    for (int ch = 1; ch < CA; ch++) {
        float4 v = ap[(size_t)ch * per_b];
        a.x += v.x; a.y += v.y; a.z += v.z; a.w += v.w;
    }
    float4 o1, o2;
    o1.x = s.x * SSCALE; o1.y = a.x * 0.125f + 0.01f;
    o1.z = s.y * SSCALE; o1.w = a.y * 0.125f + 0.01f;
    o2.x = s.z * SSCALE; o2.y = a.z * 0.125f + 0.01f;
    o2.z = s.w * SSCALE; o2.w = a.w * 0.125f + 0.01f;
    float4* out = (float4*)g_SA + (size_t)i * 2;
    out[0] = o1;
    out[1] = o2;
}

// ---------------------------------------------------------------------------
// top-5 helpers
// ---------------------------------------------------------------------------
__device__ __forceinline__ void ins5(float x, int i, float v[5], int ix[5]) {
    if (x > v[4]) {
#pragma unroll
        for (int p = 0; p < 5; p++) {
            if (x > v[p]) {
                float tv = v[p]; v[p] = x; x = tv;
                int ti = ix[p]; ix[p] = i; i = ti;
            }
        }
    }
}

__device__ __forceinline__ void head5(const float v[5], const int ix[5], int ptr,
                                      float& hv, int& hi) {
    hv = NEGINF; hi = 0x7fffffff;
    if (ptr == 0)      { hv = v[0]; hi = ix[0]; }
    else if (ptr == 1) { hv = v[1]; hi = ix[1]; }
    else if (ptr == 2) { hv = v[2]; hi = ix[2]; }
    else if (ptr == 3) { hv = v[3]; hi = ix[3]; }
    else if (ptr == 4) { hv = v[4]; hi = ix[4]; }
}

__device__ __forceinline__ void quad_merge5(const float v[5], const int ix[5],
                                            int wout[5]) {
    int ptr = 0;
#pragma unroll
    for (int t = 0; t < 5; t++) {
        float hv; int hi;
        head5(v, ix, ptr, hv, hi);
        const float mv = hv; const int mi = hi;
#pragma unroll
        for (int off = 1; off <= 2; off <<= 1) {
            float ov = __shfl_xor_sync(0xffffffffu, hv, off);
            int   oi = __shfl_xor_sync(0xffffffffu, hi, off);
            if (ov > hv || (ov == hv && oi < hi)) { hv = ov; hi = oi; }
        }
        wout[t] = hi;
        if (mv == hv && mi == hi) ptr++;
    }
}

// ---------------------------------------------------------------------------
// k_main4: per (itile128, cpair, b): 2 channels per block sharing one SA
// stream. grid (8, 8, 4) = 256 blocks.
// ---------------------------------------------------------------------------
#define KM4_SMEM (2*128*64*2 + 2*2*64*64*2 + 2*128*5*4)

__global__ void __launch_bounds__(256, 2) k_main4(const float* __restrict__ mask,
                                                  float* __restrict__ outA,
                                                  float* __restrict__ outM) {
    extern __shared__ char sm[];
    __nv_bfloat16* mi0 = (__nv_bfloat16*)sm;        // [128*64]
    __nv_bfloat16* mi1 = mi0 + 128 * 64;            // [128*64]
    __nv_bfloat16* mjb = mi1 + 128 * 64;            // [2buf][2ch][64*64]
    int* topidx = (int*)(mjb + 2 * 2 * 64 * 64);    // [2ch][128*5]

    const int tid = threadIdx.x, lane = tid & 31, w = tid >> 5;
    const int itile = blockIdx.x, cpair = blockIdx.y, b = blockIdx.z;
    const int c0 = cpair * 2;

    const __nv_bfloat16* mc0 = g_mbf + (size_t)(b * C1 + c0) * NN * DD;
    const __nv_bfloat16* mc1 = mc0 + NN * DD;
    pf_tile128(mc0 + itile * 128 * 64, mi0, tid);
    pf_tile128(mc1 + itile * 128 * 64, mi1, tid);
    CP_COMMIT();
    pf_tile64(mc0, mjb, tid);
    pf_tile64(mc1, mjb + 4096, tid);
    CP_COMMIT();
    CP_WAIT1();
    __syncthreads();

    unsigned a0[4][4], a1[4][4];
    load_afrag(mi0 + w * 16 * 64, lane, a0);
    load_afrag(mi1 + w * 16 * 64, lane, a1);

    const int lr0 = w * 16 + (lane >> 2), lr1 = lr0 + 8;
    const int gr0 = itile * 128 + lr0, gr1 = itile * 128 + lr1;

    const float* SA0 = g_SA + ((size_t)b * NN + gr0) * NN * 2;
    const float* SA1 = g_SA + ((size_t)b * NN + gr1) * NN * 2;
    float* O00 = outA + ((size_t)(b * C1 + c0) * NN + gr0) * NN;
    float* O01 = outA + ((size_t)(b * C1 + c0) * NN + gr1) * NN;
    float* O10 = O00 + (size_t)NN * NN;
    float* O11 = O01 + (size_t)NN * NN;

    // top-5 state: [ch][rowhalf]
    float v00[5], v01[5], v10[5], v11[5];
    int   i00[5], i01[5], i10[5], i11[5];
#pragma unroll
    for (int p = 0; p < 5; p++) {
        v00[p] = NEGINF; v01[p] = NEGINF; v10[p] = NEGINF; v11[p] = NEGINF;
        i00[p] = 0x7fffffff; i01[p] = 0x7fffffff; i10[p] = 0x7fffffff; i11[p] = 0x7fffffff;
    }

    const int lq = 2 * (lane & 3);

    for (int jt = 0; jt < 16; jt++) {
        if (jt < 15) {
            __nv_bfloat16* nb = mjb + ((jt + 1) & 1) * 8192;
            pf_tile64(mc0 + (jt + 1) * 64 * 64, nb, tid);
            pf_tile64(mc1 + (jt + 1) * 64 * 64, nb + 4096, tid);
            CP_COMMIT();
            CP_WAIT1();
        } else CP_WAIT0();
        __syncthreads();
        const __nv_bfloat16* bt0 = mjb + (jt & 1) * 8192;
        const __nv_bfloat16* bt1 = bt0 + 4096;

#pragma unroll
        for (int n = 0; n < 4; n++) {
            const int cb = jt * 64 + n * 16 + lq;
            // SA for this subtile (shared by both channels); issued before GEMMs
            const float4 q0 = *(const float4*)(SA0 + 2 * cb);
            const float4 q1 = *(const float4*)(SA0 + 2 * (cb + 8));
            const float4 q2 = *(const float4*)(SA1 + 2 * cb);
            const float4 q3 = *(const float4*)(SA1 + 2 * (cb + 8));

            float acc0[8] = {0.f, 0.f, 0.f, 0.f, 0.f, 0.f, 0.f, 0.f};
            subtile_mma(bt0, n * 16, lane, a0, acc0);
            float acc1[8] = {0.f, 0.f, 0.f, 0.f, 0.f, 0.f, 0.f, 0.f};
            subtile_mma(bt1, n * 16, lane, a1, acc1);

            // channel 0
            {
                float o0 = fmaf(0.01f, tanhap(q0.x * acc0[0]), q0.y);
                float o1 = fmaf(0.01f, tanhap(q0.z * acc0[1]), q0.w);
                float o4 = fmaf(0.01f, tanhap(q1.x * acc0[4]), q1.y);
                float o5 = fmaf(0.01f, tanhap(q1.z * acc0[5]), q1.w);
                float o2 = fmaf(0.01f, tanhap(q2.x * acc0[2]), q2.y);
                float o3 = fmaf(0.01f, tanhap(q2.z * acc0[3]), q2.w);
                float o6 = fmaf(0.01f, tanhap(q3.x * acc0[6]), q3.y);
                float o7 = fmaf(0.01f, tanhap(q3.z * acc0[7]), q3.w);
                *(float2*)(O00 + cb)     = make_float2(o0, o1);
                *(float2*)(O00 + cb + 8) = make_float2(o4, o5);
                *(float2*)(O01 + cb)     = make_float2(o2, o3);
                *(float2*)(O01 + cb + 8) = make_float2(o6, o7);
                ins5(o0, cb,     v00, i00); ins5(o1, cb + 1, v00, i00);
                ins5(o4, cb + 8, v00, i00); ins5(o5, cb + 9, v00, i00);
                ins5(o2, cb,     v01, i01); ins5(o3, cb + 1, v01, i01);
                ins5(o6, cb + 8, v01, i01); ins5(o7, cb + 9, v01, i01);
            }
            // channel 1
            {
                float o0 = fmaf(0.01f, tanhap(q0.x * acc1[0]), q0.y);
                float o1 = fmaf(0.01f, tanhap(q0.z * acc1[1]), q0.w);
                float o4 = fmaf(0.01f, tanhap(q1.x * acc1[4]), q1.y);
                float o5 = fmaf(0.01f, tanhap(q1.z * acc1[5]), q1.w);
                float o2 = fmaf(0.01f, tanhap(q2.x * acc1[2]), q2.y);
                float o3 = fmaf(0.01f, tanhap(q2.z * acc1[3]), q2.w);
                float o6 = fmaf(0.01f, tanhap(q3.x * acc1[6]), q3.y);
                float o7 = fmaf(0.01f, tanhap(q3.z * acc1[7]), q3.w);
                *(float2*)(O10 + cb)     = make_float2(o0, o1);
                *(float2*)(O10 + cb + 8) = make_float2(o4, o5);
                *(float2*)(O11 + cb)     = make_float2(o2, o3);
                *(float2*)(O11 + cb + 8) = make_float2(o6, o7);
                ins5(o0, cb,     v10, i10); ins5(o1, cb + 1, v10, i10);
                ins5(o4, cb + 8, v10, i10); ins5(o5, cb + 9, v10, i10);
                ins5(o2, cb,     v11, i11); ins5(o3, cb + 1, v11, i11);
                ins5(o6, cb + 8, v11, i11); ins5(o7, cb + 9, v11, i11);
            }
        }
        __syncthreads();
    }

    // merge per-row top5 across quads, stash indices
    {
        int wout[5];
        quad_merge5(v00, i00, wout);
        if ((lane & 3) == 0)
#pragma unroll
            for (int t = 0; t < 5; t++) topidx[lr0 * 5 + t] = wout[t];
        quad_merge5(v01, i01, wout);
        if ((lane & 3) == 0)
#pragma unroll
            for (int t = 0; t < 5; t++) topidx[lr1 * 5 + t] = wout[t];
        quad_merge5(v10, i10, wout);
        if ((lane & 3) == 0)
#pragma unroll
            for (int t = 0; t < 5; t++) topidx[640 + lr0 * 5 + t] = wout[t];
        quad_merge5(v11, i11, wout);
        if ((lane & 3) == 0)
#pragma unroll
            for (int t = 0; t < 5; t++) topidx[640 + lr1 * 5 + t] = wout[t];
    }
    __syncthreads();

    // gather top-5 mask rows + max (original f32 mask), both channels
#pragma unroll
    for (int ch = 0; ch < 2; ch++) {
        const float* mkb = mask + (size_t)(b * C1 + c0 + ch) * NN * DD;
        float* Mo = outM + ((size_t)(b * C1 + c0 + ch) * NN + itile * 128) * DD;
        const int* ti = topidx + ch * 640;
        for (int rr = 0; rr < 16; rr++) {
            const int lr = w * 16 + rr;
            float m0 = NEGINF, m1 = NEGINF;
#pragma unroll
            for (int p = 0; p < 5; p++) {
                const float* mr = mkb + (size_t)ti[lr * 5 + p] * DD;
                m0 = fmaxf(m0, mr[lane]);
                m1 = fmaxf(m1, mr[lane + 32]);
            }
            Mo[(size_t)lr * DD + lane] = m0;
            Mo[(size_t)lr * DD + lane + 32] = m1;
        }
    }
}

// ---------------------------------------------------------------------------
extern "C" void kernel_launch(void* const* d_in, const int* in_sizes, int n_in,
                              void* d_out, int out_size) {
    (void)in_sizes; (void)n_in; (void)out_size;
    const float* x    = (const float*)d_in[0];
    const float* A    = (const float*)d_in[1];
    const float* mask = (const float*)d_in[2];
    float* outA = (float*)d_out;
    float* outM = outA + (size_t)BB * C1 * NN * NN;

    cudaFuncSetAttribute(k_S3, cudaFuncAttributeMaxDynamicSharedMemorySize, KS3_SMEM);
    cudaFuncSetAttribute(k_main4, cudaFuncAttributeMaxDynamicSharedMemorySize, KM4_SMEM);

    k_conv<<<(NX4 + NM4 + 255) / 256, 256>>>(x, mask);
    k_S3<<<dim3(16, 8, BB), 256, KS3_SMEM>>>();
    k_sreduce2<<<BB * NN * NN / 4 / 256, 256>>>(A);
    k_main4<<<dim3(8, 8, BB), 256, KM4_SMEM>>>(mask, outA, outM);
}

// round 6
// speedup vs baseline: 1.0513x; 1.0513x over previous
#include <cuda_runtime.h>
#include <cuda_bf16.h>

// Problem constants
#define BB  4
#define CX  16
#define CA  8
#define C1  16
#define NN  1024
#define DD  64
#define NEGINF (-3.402823466e38f)

// 0.02*sigmoid(z) = 0.01 + 0.01*tanh(z/2); z = S*mm/sqrt(10)
// -> store S' = S * 0.5/sqrt(10), A' = Amean + 0.01; out = fma(0.01, tanh(S'*mm), A')
#define SSCALE 0.15811388300841898f

// Scratch (static __device__ arrays; no dynamic allocation)
__device__ __align__(16) __nv_bfloat16 g_Sp[8u * BB * NN * NN];    // 67 MB partial S (bf16)
__device__ __align__(16) float g_SA[2u * BB * NN * NN];            // 33.6 MB (S',A') interleaved
__device__ __align__(16) __nv_bfloat16 g_xbf[BB * CX * NN * DD];   // 8.4 MB
__device__ __align__(16) __nv_bfloat16 g_mbf[BB * C1 * NN * DD];   // 8.4 MB

// ---------------------------------------------------------------------------
// PTX helpers
// ---------------------------------------------------------------------------
__device__ __forceinline__ unsigned sptr(const void* p) {
    return (unsigned)__cvta_generic_to_shared(p);
}

__device__ __forceinline__ void ldsm4(unsigned a[4], unsigned addr) {
    asm volatile("ldmatrix.sync.aligned.m8n8.x4.shared.b16 {%0,%1,%2,%3}, [%4];"
                 : "=r"(a[0]), "=r"(a[1]), "=r"(a[2]), "=r"(a[3]) : "r"(addr));
}

__device__ __forceinline__ void mma16816(float c[4], const unsigned a[4],
                                         unsigned b0, unsigned b1) {
    asm volatile(
        "mma.sync.aligned.m16n8k16.row.col.f32.bf16.bf16.f32 "
        "{%0,%1,%2,%3}, {%4,%5,%6,%7}, {%8,%9}, {%0,%1,%2,%3};"
        : "+f"(c[0]), "+f"(c[1]), "+f"(c[2]), "+f"(c[3])
        : "r"(a[0]), "r"(a[1]), "r"(a[2]), "r"(a[3]), "r"(b0), "r"(b1));
}

__device__ __forceinline__ void cpasync16(unsigned dst, const void* src) {
    asm volatile("cp.async.cg.shared.global [%0], [%1], 16;" :: "r"(dst), "l"(src));
}
#define CP_COMMIT() asm volatile("cp.async.commit_group;")
#define CP_WAIT1()  asm volatile("cp.async.wait_group 1;")
#define CP_WAIT0()  asm volatile("cp.async.wait_group 0;")

__device__ __forceinline__ float tanhap(float x) {
    float r;
    asm("tanh.approx.f32 %0, %1;" : "=f"(r) : "f"(x));
    return r;
}

__device__ __forceinline__ unsigned packbf2(float a, float b) {
    __nv_bfloat162 h = __floats2bfloat162_rn(a, b);
    return *reinterpret_cast<unsigned*>(&h);
}

// ---------------------------------------------------------------------------
// Swizzled bf16 tiles: [rows][64] bf16, 128B/row; 16B chunk' = chunk ^ (row&7)
// ---------------------------------------------------------------------------
__device__ __forceinline__ void pf_tile128(const __nv_bfloat16* src,
                                           __nv_bfloat16* dst, int tid) {
#pragma unroll
    for (int q = 0; q < 4; q++) {
        int id = tid + q * 256;
        int r = id >> 3, cc = id & 7;
        cpasync16(sptr(dst + r * 64 + ((cc ^ (r & 7)) << 3)), src + r * 64 + cc * 8);
    }
}

__device__ __forceinline__ void pf_tile64(const __nv_bfloat16* src,
                                          __nv_bfloat16* dst, int tid) {
#pragma unroll
    for (int q = 0; q < 2; q++) {
        int id = tid + q * 256;
        int r = id >> 3, cc = id & 7;
        cpasync16(sptr(dst + r * 64 + ((cc ^ (r & 7)) << 3)), src + r * 64 + cc * 8);
    }
}

// A fragments for a 16-row slice, cached in regs
__device__ __forceinline__ void load_afrag(const __nv_bfloat16* xi16, int lane,
                                           unsigned a[4][4]) {
    const int ar = (lane & 7) + (((lane >> 3) & 1) << 3);
    const int ak8 = lane >> 4;
#pragma unroll
    for (int ks = 0; ks < 4; ks++)
        ldsm4(a[ks], sptr(xi16 + ar * 64 + (((2 * ks + ak8) ^ (ar & 7)) << 3)));
}

// acc[8] += A(16x64) * B(rows n0..n0+15 of 64x64 tile)^T
__device__ __forceinline__ void subtile_mma(const __nv_bfloat16* bt, int n0, int lane,
                                            const unsigned a[4][4], float acc[8]) {
    const int m = lane >> 3;
    const int br = n0 + (lane & 7) + ((m >> 1) << 3);
    const int bk8 = m & 1;
#pragma unroll
    for (int ks = 0; ks < 4; ks++) {
        unsigned b[4];
        ldsm4(b, sptr(bt + br * 64 + (((2 * ks + bk8) ^ (br & 7)) << 3)));
        mma16816(acc, a[ks], b[0], b[1]);
        mma16816(acc + 4, a[ks], b[2], b[3]);
    }
}

// ---------------------------------------------------------------------------
// Prep: bf16 conversion of x and mask in one kernel
// ---------------------------------------------------------------------------
#define NX4 (BB * CX * NN * DD / 4)
#define NM4 (BB * C1 * NN * DD / 4)
__global__ void k_conv(const float* __restrict__ x, const float* __restrict__ mask) {
    int idx = blockIdx.x * blockDim.x + threadIdx.x;
    const float4* src;
    uint2* dst;
    int i;
    if (idx < NX4) { src = (const float4*)x; dst = (uint2*)g_xbf; i = idx; }
    else if (idx < NX4 + NM4) { src = (const float4*)mask; dst = (uint2*)g_mbf; i = idx - NX4; }
    else return;
    float4 v = src[i];
    uint2 u;
    u.x = packbf2(v.x, v.y);
    u.y = packbf2(v.z, v.w);
    dst[i] = u;
}

// ---------------------------------------------------------------------------
// k_S3: partial S for 2 channels, 64-row tiles.
// grid (itile=16, cg=8, b=4) = 512 blocks, 256 thr.
// ---------------------------------------------------------------------------
#define KS3_SMEM (2*64*64*2 + 2*2*64*64*2 + 2*64*4 + 2*64*2*4 + 2*64*4)

__global__ void __launch_bounds__(256, 3) k_S3() {
    extern __shared__ char sm[];
    __nv_bfloat16* xi  = (__nv_bfloat16*)sm;            // [2ch][64*64]
    __nv_bfloat16* xjb = xi + 2 * 64 * 64;              // [2buf][2ch][64*64]
    float* P  = (float*)(xjb + 2 * 2 * 64 * 64);        // [2][64]
    float* Zw = P + 2 * 64;                             // [2][64][2]
    float* Zi = Zw + 2 * 64 * 2;                        // [2][64]

    const int tid = threadIdx.x, lane = tid & 31, w = tid >> 5;
    const int wr = w & 3, wc = w >> 2;
    const int itile = blockIdx.x, cg = blockIdx.y, b = blockIdx.z;

    const __nv_bfloat16* xc0 = g_xbf + (size_t)(b * CX + cg * 2) * NN * DD;
    const __nv_bfloat16* xc1 = xc0 + NN * DD;

    pf_tile64(xc0 + itile * 64 * 64, xi, tid);
    pf_tile64(xc1 + itile * 64 * 64, xi + 64 * 64, tid);
    CP_COMMIT();
    pf_tile64(xc0, xjb, tid);
    pf_tile64(xc1, xjb + 64 * 64, tid);
    CP_COMMIT();
    CP_WAIT1();
    __syncthreads();

    // P = ||row||^2 from bf16 values
    if (tid < 128) {
        int c = tid >> 6, r = tid & 63;
        const __nv_bfloat16* row = xi + c * 4096 + r * 64;
        float s = 0.f;
#pragma unroll
        for (int cc = 0; cc < 8; cc++) {
            const __nv_bfloat16* ch = row + ((cc ^ (r & 7)) << 3);
#pragma unroll
            for (int e = 0; e < 8; e++) {
                float v = __bfloat162float(ch[e]);
                s += v * v;
            }
        }
        P[c * 64 + r] = s;
    }
    __syncthreads();

    unsigned a0[4][4], a1[4][4];
    load_afrag(xi + wr * 16 * 64, lane, a0);
    load_afrag(xi + 4096 + wr * 16 * 64, lane, a1);

    const int lr0 = wr * 16 + (lane >> 2), lr1 = lr0 + 8;
    const float p00 = P[lr0], p01 = P[lr1], p10 = P[64 + lr0], p11 = P[64 + lr1];

    // ---- Pass Z ----
    float z00 = 0.f, z01 = 0.f, z10 = 0.f, z11 = 0.f;
    for (int jt = 0; jt < 16; jt++) {
        if (jt < 15) {
            __nv_bfloat16* nb = xjb + ((jt + 1) & 1) * 8192;
            pf_tile64(xc0 + (jt + 1) * 64 * 64, nb, tid);
            pf_tile64(xc1 + (jt + 1) * 64 * 64, nb + 4096, tid);
            CP_COMMIT(); CP_WAIT1();
        } else CP_WAIT0();
        __syncthreads();
        const __nv_bfloat16* bt = xjb + (jt & 1) * 8192;
#pragma unroll
        for (int nn = 0; nn < 2; nn++) {
            const int n0 = (wc * 2 + nn) * 16;
            {
                float acc[8] = {0.f, 0.f, 0.f, 0.f, 0.f, 0.f, 0.f, 0.f};
                subtile_mma(bt, n0, lane, a0, acc);
                z00 += __expf(acc[0] - p00) + __expf(acc[1] - p00)
                     + __expf(acc[4] - p00) + __expf(acc[5] - p00);
                z01 += __expf(acc[2] - p01) + __expf(acc[3] - p01)
                     + __expf(acc[6] - p01) + __expf(acc[7] - p01);
            }
            {
                float acc[8] = {0.f, 0.f, 0.f, 0.f, 0.f, 0.f, 0.f, 0.f};
                subtile_mma(bt + 4096, n0, lane, a1, acc);
                z10 += __expf(acc[0] - p10) + __expf(acc[1] - p10)
                     + __expf(acc[4] - p10) + __expf(acc[5] - p10);
                z11 += __expf(acc[2] - p11) + __expf(acc[3] - p11)
                     + __expf(acc[6] - p11) + __expf(acc[7] - p11);
            }
        }
        __syncthreads();
    }
    z00 += __shfl_xor_sync(0xffffffffu, z00, 1); z00 += __shfl_xor_sync(0xffffffffu, z00, 2);
    z01 += __shfl_xor_sync(0xffffffffu, z01, 1); z01 += __shfl_xor_sync(0xffffffffu, z01, 2);
    z10 += __shfl_xor_sync(0xffffffffu, z10, 1); z10 += __shfl_xor_sync(0xffffffffu, z10, 2);
    z11 += __shfl_xor_sync(0xffffffffu, z11, 1); z11 += __shfl_xor_sync(0xffffffffu, z11, 2);
    if ((lane & 3) == 0) {
        Zw[lr0 * 2 + wc]       = z00;
        Zw[lr1 * 2 + wc]       = z01;
        Zw[128 + lr0 * 2 + wc] = z10;
        Zw[128 + lr1 * 2 + wc] = z11;
    }
    __syncthreads();
    if (tid < 128) {
        int c = tid >> 6, r = tid & 63;
        Zi[c * 64 + r] = 1.f / (16.f * (Zw[c * 128 + r * 2] + Zw[c * 128 + r * 2 + 1]));
    }
    pf_tile64(xc0, xjb, tid);
    pf_tile64(xc1, xjb + 4096, tid);
    CP_COMMIT();
    __syncthreads();

    const float zi00 = Zi[lr0], zi01 = Zi[lr1];
    const float zi10 = Zi[64 + lr0], zi11 = Zi[64 + lr1];

    __nv_bfloat16* spBase = g_Sp + (size_t)(cg * BB + b) * NN * NN + (size_t)(itile * 64) * NN;

    for (int jt = 0; jt < 16; jt++) {
        if (jt < 15) {
            __nv_bfloat16* nb = xjb + ((jt + 1) & 1) * 8192;
            pf_tile64(xc0 + (jt + 1) * 64 * 64, nb, tid);
            pf_tile64(xc1 + (jt + 1) * 64 * 64, nb + 4096, tid);
            CP_COMMIT(); CP_WAIT1();
        } else CP_WAIT0();
        __syncthreads();
        const __nv_bfloat16* bt = xjb + (jt & 1) * 8192;

#pragma unroll
        for (int nn = 0; nn < 2; nn++) {
            const int n = wc * 2 + nn;
            float Sa[8];
#pragma unroll
            for (int k = 0; k < 8; k++) Sa[k] = 0.f;
            {
                float acc[8] = {0.f, 0.f, 0.f, 0.f, 0.f, 0.f, 0.f, 0.f};
                subtile_mma(bt, n * 16, lane, a0, acc);
                Sa[0] += __expf(acc[0] - p00) * zi00;
                Sa[1] += __expf(acc[1] - p00) * zi00;
                Sa[4] += __expf(acc[4] - p00) * zi00;
                Sa[5] += __expf(acc[5] - p00) * zi00;
                Sa[2] += __expf(acc[2] - p01) * zi01;
                Sa[3] += __expf(acc[3] - p01) * zi01;
                Sa[6] += __expf(acc[6] - p01) * zi01;
                Sa[7] += __expf(acc[7] - p01) * zi01;
            }
            {
                float acc[8] = {0.f, 0.f, 0.f, 0.f, 0.f, 0.f, 0.f, 0.f};
                subtile_mma(bt + 4096, n * 16, lane, a1, acc);
                Sa[0] += __expf(acc[0] - p10) * zi10;
                Sa[1] += __expf(acc[1] - p10) * zi10;
                Sa[4] += __expf(acc[4] - p10) * zi10;
                Sa[5] += __expf(acc[5] - p10) * zi10;
                Sa[2] += __expf(acc[2] - p11) * zi11;
                Sa[3] += __expf(acc[3] - p11) * zi11;
                Sa[6] += __expf(acc[6] - p11) * zi11;
                Sa[7] += __expf(acc[7] - p11) * zi11;
            }
            const int cb = jt * 64 + n * 16 + 2 * (lane & 3);
            *(unsigned*)(spBase + (size_t)lr0 * NN + cb)     = packbf2(Sa[0], Sa[1]);
            *(unsigned*)(spBase + (size_t)lr0 * NN + cb + 8) = packbf2(Sa[4], Sa[5]);
            *(unsigned*)(spBase + (size_t)lr1 * NN + cb)     = packbf2(Sa[2], Sa[3]);
            *(unsigned*)(spBase + (size_t)lr1 * NN + cb + 8) = packbf2(Sa[6], Sa[7]);
        }
        __syncthreads();
    }
}

// ---------------------------------------------------------------------------
// k_sreduce2: sum 8 bf16 partial S slices + mean of A over CA, write
// interleaved (S*SSCALE, Amean+0.01) pairs.
// ---------------------------------------------------------------------------
__global__ void k_sreduce2(const float* __restrict__ A) {
    int i = blockIdx.x * 256 + threadIdx.x;   // group of 4 elements
    const int per_b = NN * NN / 4;
    int b = i / per_b;
    int r = i - b * per_b;

    const uint2* sp = (const uint2*)g_Sp;
    float4 s = make_float4(0.f, 0.f, 0.f, 0.f);
#pragma unroll
    for (int g = 0; g < 8; g++) {
        uint2 u = sp[(size_t)(g * BB + b) * per_b + r];
        __nv_bfloat162 h0 = *reinterpret_cast<__nv_bfloat162*>(&u.x);
        __nv_bfloat162 h1 = *reinterpret_cast<__nv_bfloat162*>(&u.y);
        float2 f0 = __bfloat1622float2(h0);
        float2 f1 = __bfloat1622float2(h1);
        s.x += f0.x; s.y += f0.y; s.z += f1.x; s.w += f1.y;
    }
    const float4* ap = (const float4*)A + (size_t)b * CA * per_b + r;
    float4 a = ap[0];
#pragma unroll
    for (int ch = 1; ch < CA; ch++) {
        float4 v = ap[(size_t)ch * per_b];
        a.x += v.x; a.y += v.y; a.z += v.z; a.w += v.w;
    }
    float4 o1, o2;
    o1.x = s.x * SSCALE; o1.y = a.x * 0.125f + 0.01f;
    o1.z = s.y * SSCALE; o1.w = a.y * 0.125f + 0.01f;
    o2.x = s.z * SSCALE; o2.y = a.z * 0.125f + 0.01f;
    o2.z = s.w * SSCALE; o2.w = a.w * 0.125f + 0.01f;
    float4* out = (float4*)g_SA + (size_t)i * 2;
    out[0] = o1;
    out[1] = o2;
}

// ---------------------------------------------------------------------------
// top-5 helpers
// ---------------------------------------------------------------------------
__device__ __forceinline__ void ins5(float x, int i, float v[5], int ix[5]) {
#pragma unroll
    for (int p = 0; p < 5; p++) {
        if (x > v[p]) {
            float tv = v[p]; v[p] = x; x = tv;
            int ti = ix[p]; ix[p] = i; i = ti;
        }
    }
}

__device__ __forceinline__ void head5(const float v[5], const int ix[5], int ptr,
                                      float& hv, int& hi) {
    hv = NEGINF; hi = 0x7fffffff;
    if (ptr == 0)      { hv = v[0]; hi = ix[0]; }
    else if (ptr == 1) { hv = v[1]; hi = ix[1]; }
    else if (ptr == 2) { hv = v[2]; hi = ix[2]; }
    else if (ptr == 3) { hv = v[3]; hi = ix[3]; }
    else if (ptr == 4) { hv = v[4]; hi = ix[4]; }
}

__device__ __forceinline__ void quad_merge5(const float v[5], const int ix[5],
                                            int wout[5]) {
    int ptr = 0;
#pragma unroll
    for (int t = 0; t < 5; t++) {
        float hv; int hi;
        head5(v, ix, ptr, hv, hi);
        const float mv = hv; const int mi = hi;
#pragma unroll
        for (int off = 1; off <= 2; off <<= 1) {
            float ov = __shfl_xor_sync(0xffffffffu, hv, off);
            int   oi = __shfl_xor_sync(0xffffffffu, hi, off);
            if (ov > hv || (ov == hv && oi < hi)) { hv = ov; hi = oi; }
        }
        wout[t] = hi;
        if (mv == hv && mi == hi) ptr++;
    }
}

// ---------------------------------------------------------------------------
// k_main5: per (itile128, cpair, b): 2 channels per block sharing one SA
// stream; aggregated-max + rare-branch top-5. grid (8, 8, 4) = 256 blocks.
// ---------------------------------------------------------------------------
#define KM4_SMEM (2*128*64*2 + 2*2*64*64*2 + 2*128*5*4)

__global__ void __launch_bounds__(256, 2) k_main5(const float* __restrict__ mask,
                                                  float* __restrict__ outA,
                                                  float* __restrict__ outM) {
    extern __shared__ char sm[];
    __nv_bfloat16* mi0 = (__nv_bfloat16*)sm;        // [128*64]
    __nv_bfloat16* mi1 = mi0 + 128 * 64;            // [128*64]
    __nv_bfloat16* mjb = mi1 + 128 * 64;            // [2buf][2ch][64*64]
    int* topidx = (int*)(mjb + 2 * 2 * 64 * 64);    // [2ch][128*5]

    const int tid = threadIdx.x, lane = tid & 31, w = tid >> 5;
    const int itile = blockIdx.x, cpair = blockIdx.y, b = blockIdx.z;
    const int c0 = cpair * 2;

    const __nv_bfloat16* mc0 = g_mbf + (size_t)(b * C1 + c0) * NN * DD;
    const __nv_bfloat16* mc1 = mc0 + NN * DD;
    pf_tile128(mc0 + itile * 128 * 64, mi0, tid);
    pf_tile128(mc1 + itile * 128 * 64, mi1, tid);
    CP_COMMIT();
    pf_tile64(mc0, mjb, tid);
    pf_tile64(mc1, mjb + 4096, tid);
    CP_COMMIT();
    CP_WAIT1();
    __syncthreads();

    unsigned a0[4][4], a1[4][4];
    load_afrag(mi0 + w * 16 * 64, lane, a0);
    load_afrag(mi1 + w * 16 * 64, lane, a1);

    const int lr0 = w * 16 + (lane >> 2), lr1 = lr0 + 8;
    const int gr0 = itile * 128 + lr0, gr1 = itile * 128 + lr1;

    const float* SA0 = g_SA + ((size_t)b * NN + gr0) * NN * 2;
    const float* SA1 = g_SA + ((size_t)b * NN + gr1) * NN * 2;
    float* O00 = outA + ((size_t)(b * C1 + c0) * NN + gr0) * NN;
    float* O01 = outA + ((size_t)(b * C1 + c0) * NN + gr1) * NN;
    float* O10 = O00 + (size_t)NN * NN;
    float* O11 = O01 + (size_t)NN * NN;

    // top-5 state: [ch][rowhalf]; vm = current 5th-best (hot register)
    float v00[5], v01[5], v10[5], v11[5];
    int   i00[5], i01[5], i10[5], i11[5];
#pragma unroll
    for (int p = 0; p < 5; p++) {
        v00[p] = NEGINF; v01[p] = NEGINF; v10[p] = NEGINF; v11[p] = NEGINF;
        i00[p] = 0x7fffffff; i01[p] = 0x7fffffff; i10[p] = 0x7fffffff; i11[p] = 0x7fffffff;
    }
    float vm00 = NEGINF, vm01 = NEGINF, vm10 = NEGINF, vm11 = NEGINF;

    const int lq = 2 * (lane & 3);

    for (int jt = 0; jt < 16; jt++) {
        if (jt < 15) {
            __nv_bfloat16* nb = mjb + ((jt + 1) & 1) * 8192;
            pf_tile64(mc0 + (jt + 1) * 64 * 64, nb, tid);
            pf_tile64(mc1 + (jt + 1) * 64 * 64, nb + 4096, tid);
            CP_COMMIT();
            CP_WAIT1();
        } else CP_WAIT0();
        __syncthreads();
        const __nv_bfloat16* bt0 = mjb + (jt & 1) * 8192;
        const __nv_bfloat16* bt1 = bt0 + 4096;

#pragma unroll
        for (int n = 0; n < 4; n++) {
            const int cb = jt * 64 + n * 16 + lq;
            // SA for this subtile (shared by both channels); issued before GEMMs
            const float4 q0 = *(const float4*)(SA0 + 2 * cb);
            const float4 q1 = *(const float4*)(SA0 + 2 * (cb + 8));
            const float4 q2 = *(const float4*)(SA1 + 2 * cb);
            const float4 q3 = *(const float4*)(SA1 + 2 * (cb + 8));

            float acc0[8] = {0.f, 0.f, 0.f, 0.f, 0.f, 0.f, 0.f, 0.f};
            subtile_mma(bt0, n * 16, lane, a0, acc0);
            float acc1[8] = {0.f, 0.f, 0.f, 0.f, 0.f, 0.f, 0.f, 0.f};
            subtile_mma(bt1, n * 16, lane, a1, acc1);

            // channel 0
            {
                float o0 = fmaf(0.01f, tanhap(q0.x * acc0[0]), q0.y);
                float o1 = fmaf(0.01f, tanhap(q0.z * acc0[1]), q0.w);
                float o4 = fmaf(0.01f, tanhap(q1.x * acc0[4]), q1.y);
                float o5 = fmaf(0.01f, tanhap(q1.z * acc0[5]), q1.w);
                float o2 = fmaf(0.01f, tanhap(q2.x * acc0[2]), q2.y);
                float o3 = fmaf(0.01f, tanhap(q2.z * acc0[3]), q2.w);
                float o6 = fmaf(0.01f, tanhap(q3.x * acc0[6]), q3.y);
                float o7 = fmaf(0.01f, tanhap(q3.z * acc0[7]), q3.w);
                *(float2*)(O00 + cb)     = make_float2(o0, o1);
                *(float2*)(O00 + cb + 8) = make_float2(o4, o5);
                *(float2*)(O01 + cb)     = make_float2(o2, o3);
                *(float2*)(O01 + cb + 8) = make_float2(o6, o7);
                float mA = fmaxf(fmaxf(o0, o1), fmaxf(o4, o5));
                if (mA > vm00) {
                    ins5(o0, cb,     v00, i00); ins5(o1, cb + 1, v00, i00);
                    ins5(o4, cb + 8, v00, i00); ins5(o5, cb + 9, v00, i00);
                    vm00 = v00[4];
                }
                float mB = fmaxf(fmaxf(o2, o3), fmaxf(o6, o7));
                if (mB > vm01) {
                    ins5(o2, cb,     v01, i01); ins5(o3, cb + 1, v01, i01);
                    ins5(o6, cb + 8, v01, i01); ins5(o7, cb + 9, v01, i01);
                    vm01 = v01[4];
                }
            }
            // channel 1
            {
                float o0 = fmaf(0.01f, tanhap(q0.x * acc1[0]), q0.y);
                float o1 = fmaf(0.01f, tanhap(q0.z * acc1[1]), q0.w);
                float o4 = fmaf(0.01f, tanhap(q1.x * acc1[4]), q1.y);
                float o5 = fmaf(0.01f, tanhap(q1.z * acc1[5]), q1.w);
                float o2 = fmaf(0.01f, tanhap(q2.x * acc1[2]), q2.y);
                float o3 = fmaf(0.01f, tanhap(q2.z * acc1[3]), q2.w);
                float o6 = fmaf(0.01f, tanhap(q3.x * acc1[6]), q3.y);
                float o7 = fmaf(0.01f, tanhap(q3.z * acc1[7]), q3.w);
                *(float2*)(O10 + cb)     = make_float2(o0, o1);
                *(float2*)(O10 + cb + 8) = make_float2(o4, o5);
                *(float2*)(O11 + cb)     = make_float2(o2, o3);
                *(float2*)(O11 + cb + 8) = make_float2(o6, o7);
                float mA = fmaxf(fmaxf(o0, o1), fmaxf(o4, o5));
                if (mA > vm10) {
                    ins5(o0, cb,     v10, i10); ins5(o1, cb + 1, v10, i10);
                    ins5(o4, cb + 8, v10, i10); ins5(o5, cb + 9, v10, i10);
                    vm10 = v10[4];
                }
                float mB = fmaxf(fmaxf(o2, o3), fmaxf(o6, o7));
                if (mB > vm11) {
                    ins5(o2, cb,     v11, i11); ins5(o3, cb + 1, v11, i11);
                    ins5(o6, cb + 8, v11, i11); ins5(o7, cb + 9, v11, i11);
                    vm11 = v11[4];
                }
            }
        }
        __syncthreads();
    }

    // merge per-row top5 across quads, stash indices
    {
        int wout[5];
        quad_merge5(v00, i00, wout);
        if ((lane & 3) == 0)
#pragma unroll
            for (int t = 0; t < 5; t++) topidx[lr0 * 5 + t] = wout[t];
        quad_merge5(v01, i01, wout);
        if ((lane & 3) == 0)
#pragma unroll
            for (int t = 0; t < 5; t++) topidx[lr1 * 5 + t] = wout[t];
        quad_merge5(v10, i10, wout);
        if ((lane & 3) == 0)
#pragma unroll
            for (int t = 0; t < 5; t++) topidx[640 + lr0 * 5 + t] = wout[t];
        quad_merge5(v11, i11, wout);
        if ((lane & 3) == 0)
#pragma unroll
            for (int t = 0; t < 5; t++) topidx[640 + lr1 * 5 + t] = wout[t];
    }
    __syncthreads();

    // gather top-5 mask rows + max (original f32 mask), both channels
#pragma unroll
    for (int ch = 0; ch < 2; ch++) {
        const float* mkb = mask + (size_t)(b * C1 + c0 + ch) * NN * DD;
        float* Mo = outM + ((size_t)(b * C1 + c0 + ch) * NN + itile * 128) * DD;
        const int* ti = topidx + ch * 640;
        for (int rr = 0; rr < 16; rr++) {
            const int lr = w * 16 + rr;
            float m0 = NEGINF, m1 = NEGINF;
#pragma unroll
            for (int p = 0; p < 5; p++) {
                const float* mr = mkb + (size_t)ti[lr * 5 + p] * DD;
                m0 = fmaxf(m0, mr[lane]);
                m1 = fmaxf(m1, mr[lane + 32]);
            }
            Mo[(size_t)lr * DD + lane] = m0;
            Mo[(size_t)lr * DD + lane + 32] = m1;
        }
    }
}

// ---------------------------------------------------------------------------
extern "C" void kernel_launch(void* const* d_in, const int* in_sizes, int n_in,
                              void* d_out, int out_size) {
    (void)in_sizes; (void)n_in; (void)out_size;
    const float* x    = (const float*)d_in[0];
    const float* A    = (const float*)d_in[1];
    const float* mask = (const float*)d_in[2];
    float* outA = (float*)d_out;
    float* outM = outA + (size_t)BB * C1 * NN * NN;

    cudaFuncSetAttribute(k_S3, cudaFuncAttributeMaxDynamicSharedMemorySize, KS3_SMEM);
    cudaFuncSetAttribute(k_main5, cudaFuncAttributeMaxDynamicSharedMemorySize, KM4_SMEM);

    k_conv<<<(NX4 + NM4 + 255) / 256, 256>>>(x, mask);
    k_S3<<<dim3(16, 8, BB), 256, KS3_SMEM>>>();
    k_sreduce2<<<BB * NN * NN / 4 / 256, 256>>>(A);
    k_main5<<<dim3(8, 8, BB), 256, KM4_SMEM>>>(mask, outA, outM);
}